// round 6
// baseline (speedup 1.0000x reference)
#include <cuda_runtime.h>
#include <cuda_fp16.h>
#include <mma.h>
#include <math.h>
#include <stdint.h>

using namespace nvcuda;

#define NN 100000
#define EE 1600000
#define NEG 0.01f

// ---------------- scratch (device globals) ---------------------------------
__device__ __half2 g_bufA[NN * 32];  // fp16 pre-scaled features (ping)
__device__ __half2 g_bufB[NN * 32];  // fp16 pre-scaled features (pong)
__device__ int   g_cnt[NN];
__device__ int   g_rowptr[NN];
__device__ int   g_pos[NN];
__device__ int   g_col[EE];
__device__ float g_dinv[NN];
__device__ int   g_bsum[128];

// ---------------- CSR build ------------------------------------------------
__global__ void k_zero_cnt() {
    int i = blockIdx.x * blockDim.x + threadIdx.x;
    if (i < NN) g_cnt[i] = 0;
}

__global__ void k_hist(const int* __restrict__ dst) {
    int t = blockIdx.x * blockDim.x + threadIdx.x;
    if (t * 4 < EE) {
        int4 d = ((const int4*)dst)[t];
        atomicAdd(&g_cnt[d.x], 1);
        atomicAdd(&g_cnt[d.y], 1);
        atomicAdd(&g_cnt[d.z], 1);
        atomicAdd(&g_cnt[d.w], 1);
    }
}

__global__ void k_scanA() {
    __shared__ int s[1024];
    int tid = threadIdx.x;
    int i = blockIdx.x * 1024 + tid;
    int v = (i < NN) ? g_cnt[i] : 0;
    if (i < NN) g_dinv[i] = rsqrtf((float)(v + 1));
    s[tid] = v;
    __syncthreads();
    #pragma unroll
    for (int off = 1; off < 1024; off <<= 1) {
        int t = (tid >= off) ? s[tid - off] : 0;
        __syncthreads();
        s[tid] += t;
        __syncthreads();
    }
    if (i < NN) g_rowptr[i] = s[tid] - v;
    if (tid == 1023) g_bsum[blockIdx.x] = s[1023];
}

__global__ void k_scanB(int nb) {
    int lane = threadIdx.x;
    int base = lane * 4;
    int v0 = (base + 0 < nb) ? g_bsum[base + 0] : 0;
    int v1 = (base + 1 < nb) ? g_bsum[base + 1] : 0;
    int v2 = (base + 2 < nb) ? g_bsum[base + 2] : 0;
    int v3 = (base + 3 < nb) ? g_bsum[base + 3] : 0;
    int s1 = v0 + v1, s2 = s1 + v2, s3 = s2 + v3;
    int tot = s3;
    int run = tot;
    #pragma unroll
    for (int off = 1; off < 32; off <<= 1) {
        int t = __shfl_up_sync(0xffffffffu, run, off);
        if (lane >= off) run += t;
    }
    int excl = run - tot;
    if (base + 0 < nb) g_bsum[base + 0] = excl;
    if (base + 1 < nb) g_bsum[base + 1] = excl + v0;
    if (base + 2 < nb) g_bsum[base + 2] = excl + s1;
    if (base + 3 < nb) g_bsum[base + 3] = excl + s2;
}

// rowptr finalize + pos init + prep layer-1 features: p = dinv[row] * x (fp16)
__global__ void k_scanC_prep(const float2* __restrict__ x, __half2* __restrict__ p) {
    int gid = blockIdx.x * blockDim.x + threadIdx.x;   // 6250*256 = 1.6M
    if (gid < NN) {
        int rp = g_rowptr[gid] + g_bsum[gid >> 10];
        g_rowptr[gid] = rp;
        g_pos[gid] = rp;
    }
    int total = NN * 32;
    for (int i = gid; i < total; i += gridDim.x * blockDim.x) {
        int row = i >> 5;
        float di = g_dinv[row];
        float2 v = x[i];
        p[i] = __floats2half2_rn(di * v.x, di * v.y);
    }
}

__global__ void k_scatter(const int* __restrict__ src, const int* __restrict__ dst) {
    int t = blockIdx.x * blockDim.x + threadIdx.x;
    if (t * 4 < EE) {
        int4 d = ((const int4*)dst)[t];
        int4 s = ((const int4*)src)[t];
        int p0 = atomicAdd(&g_pos[d.x], 1);
        int p1 = atomicAdd(&g_pos[d.y], 1);
        int p2 = atomicAdd(&g_pos[d.z], 1);
        int p3 = atomicAdd(&g_pos[d.w], 1);
        g_col[p0] = s.x;
        g_col[p1] = s.y;
        g_col[p2] = s.z;
        g_col[p3] = s.w;
    }
}

// ---------------- Fused layer: agg -> WMMA GEMM -> bias+LeakyReLU ----------
// Input: p (fp16 pre-scaled features, p = dinv*feat). Per block: 128 dst rows.
// Phase 1: z[r] = dinv[r] * (sum_{src in N(r)} p[src] + p[r])   (smem, fp16)
// Phase 2: h = z @ W; out = LeakyReLU(h + b); store dinv*out fp16 (or fp32 final).
template<bool FINAL>
__global__ void __launch_bounds__(256) k_layer(
    const __half2* __restrict__ p, const float* __restrict__ W,
    const float* __restrict__ bias, void* __restrict__ outv) {
    __shared__ __align__(16) half zs[128 * 64];   // aggregated tile (A)
    __shared__ __align__(16) half Bs[64 * 64];    // W fp16
    __shared__ float bias_s[64];
    int tid  = threadIdx.x;
    int warp = tid >> 5, lane = tid & 31;
    int rowbase = blockIdx.x * 128;

    // load W -> Bs
    #pragma unroll
    for (int k = 0; k < 4; k++) {
        int i = tid + k * 256;
        float4 w = ((const float4*)W)[i];
        __half2 h0 = __floats2half2_rn(w.x, w.y);
        __half2 h1 = __floats2half2_rn(w.z, w.w);
        *(uint2*)(Bs + i * 4) = make_uint2(*(uint32_t*)&h0, *(uint32_t*)&h1);
    }
    if (tid < 64) bias_s[tid] = bias[tid];

    // ---- phase 1: aggregation, warp handles 16 rows ----
    int row0 = rowbase + warp * 16;
    // coalesced row metadata: lanes 0-15 -> rowptr, lanes 16-31 -> cnt
    int meta = 0;
    {
        int r = row0 + (lane & 15);
        if (r < NN) meta = (lane < 16) ? g_rowptr[r] : g_cnt[r];
    }
    for (int r16 = 0; r16 < 16; r16++) {
        int row = row0 + r16;
        float a0 = 0.f, a1 = 0.f;
        if (row < NN) {
            int start = __shfl_sync(0xffffffffu, meta, r16);
            int cnt   = __shfl_sync(0xffffffffu, meta, 16 + r16);
            const int* cp = g_col + start;
            for (int base = 0; base < cnt; base += 32) {
                int m = cnt - base; if (m > 32) m = 32;
                int idx = (lane < m) ? cp[base + lane] : 0;
                int j = 0;
                for (; j + 4 <= m; j += 4) {
                    int s0 = __shfl_sync(0xffffffffu, idx, j + 0);
                    int s1 = __shfl_sync(0xffffffffu, idx, j + 1);
                    int s2 = __shfl_sync(0xffffffffu, idx, j + 2);
                    int s3 = __shfl_sync(0xffffffffu, idx, j + 3);
                    float2 f0 = __half22float2(p[(size_t)s0 * 32 + lane]);
                    float2 f1 = __half22float2(p[(size_t)s1 * 32 + lane]);
                    float2 f2 = __half22float2(p[(size_t)s2 * 32 + lane]);
                    float2 f3 = __half22float2(p[(size_t)s3 * 32 + lane]);
                    a0 += f0.x + f1.x + f2.x + f3.x;
                    a1 += f0.y + f1.y + f2.y + f3.y;
                }
                for (; j < m; j++) {
                    int s = __shfl_sync(0xffffffffu, idx, j);
                    float2 f = __half22float2(p[(size_t)s * 32 + lane]);
                    a0 += f.x; a1 += f.y;
                }
            }
            float2 ps = __half22float2(p[(size_t)row * 32 + lane]);  // self (pre-scaled)
            float di = g_dinv[row];
            a0 = di * (a0 + ps.x);
            a1 = di * (a1 + ps.y);
        }
        *(__half2*)(zs + (warp * 16 + r16) * 64 + lane * 2) = __floats2half2_rn(a0, a1);
    }
    __syncthreads();

    // ---- phase 2: WMMA z @ W ----
    wmma::fragment<wmma::accumulator, 16, 16, 16, float> c[4];
    #pragma unroll
    for (int nt = 0; nt < 4; nt++) wmma::fill_fragment(c[nt], 0.0f);
    const half* arow = zs + warp * 16 * 64;
    #pragma unroll
    for (int k0 = 0; k0 < 64; k0 += 16) {
        wmma::fragment<wmma::matrix_a, 16, 16, 16, half, wmma::row_major> a;
        wmma::load_matrix_sync(a, arow + k0, 64);
        #pragma unroll
        for (int nt = 0; nt < 4; nt++) {
            wmma::fragment<wmma::matrix_b, 16, 16, 16, half, wmma::row_major> b;
            wmma::load_matrix_sync(b, Bs + k0 * 64 + nt * 16, 64);
            wmma::mma_sync(c[nt], a, b, c[nt]);
        }
    }
    __syncthreads();   // all warps done reading zs; reuse as staging

    // ---- epilogue ----
    float* Cst = (float*)zs + warp * 256;
    int r = lane >> 1;
    int chalf = (lane & 1) * 8;
    int grow = rowbase + warp * 16 + r;
    float di = (grow < NN) ? g_dinv[grow] : 0.f;
    #pragma unroll
    for (int nt = 0; nt < 4; nt++) {
        wmma::store_matrix_sync(Cst, c[nt], 16, wmma::mem_row_major);
        __syncwarp();
        if (grow < NN) {
            int c0 = nt * 16 + chalf;
            float4 v0 = *(const float4*)(Cst + r * 16 + chalf);
            float4 v1 = *(const float4*)(Cst + r * 16 + chalf + 4);
            float t0 = v0.x + bias_s[c0 + 0];
            float t1 = v0.y + bias_s[c0 + 1];
            float t2 = v0.z + bias_s[c0 + 2];
            float t3 = v0.w + bias_s[c0 + 3];
            float t4 = v1.x + bias_s[c0 + 4];
            float t5 = v1.y + bias_s[c0 + 5];
            float t6 = v1.z + bias_s[c0 + 6];
            float t7 = v1.w + bias_s[c0 + 7];
            t0 = (t0 >= 0.f) ? t0 : NEG * t0;
            t1 = (t1 >= 0.f) ? t1 : NEG * t1;
            t2 = (t2 >= 0.f) ? t2 : NEG * t2;
            t3 = (t3 >= 0.f) ? t3 : NEG * t3;
            t4 = (t4 >= 0.f) ? t4 : NEG * t4;
            t5 = (t5 >= 0.f) ? t5 : NEG * t5;
            t6 = (t6 >= 0.f) ? t6 : NEG * t6;
            t7 = (t7 >= 0.f) ? t7 : NEG * t7;
            if (FINAL) {
                float* orow = (float*)outv + (size_t)grow * 64 + c0;
                *(float4*)(orow)     = make_float4(t0, t1, t2, t3);
                *(float4*)(orow + 4) = make_float4(t4, t5, t6, t7);
            } else {
                __half2 h0 = __floats2half2_rn(di * t0, di * t1);
                __half2 h1 = __floats2half2_rn(di * t2, di * t3);
                __half2 h2 = __floats2half2_rn(di * t4, di * t5);
                __half2 h3 = __floats2half2_rn(di * t6, di * t7);
                *(uint4*)((__half2*)outv + (size_t)grow * 32 + c0 / 2) =
                    make_uint4(*(uint32_t*)&h0, *(uint32_t*)&h1,
                               *(uint32_t*)&h2, *(uint32_t*)&h3);
            }
        }
        __syncwarp();
    }
}

// ---------------- launch ----------------------------------------------------
extern "C" void kernel_launch(void* const* d_in, const int* in_sizes, int n_in,
                              void* d_out, int out_size) {
    (void)in_sizes; (void)n_in; (void)out_size;
    const float* x  = (const float*)d_in[0];
    const int*   ei = (const int*)d_in[1];
    const int* src = ei;
    const int* dst = ei + EE;
    const float* Wt[4] = { (const float*)d_in[2], (const float*)d_in[4],
                           (const float*)d_in[6], (const float*)d_in[8] };
    const float* bt[4] = { (const float*)d_in[3], (const float*)d_in[5],
                           (const float*)d_in[7], (const float*)d_in[9] };

    __half2 *p_a, *p_b;
    cudaGetSymbolAddress((void**)&p_a, g_bufA);
    cudaGetSymbolAddress((void**)&p_b, g_bufB);

    const int NB_SCAN = (NN + 1023) / 1024;    // 98
    const int NB_N256 = (NN + 255) / 256;      // 391
    const int NB_E4   = (EE / 4 + 255) / 256;  // 1563

    k_zero_cnt<<<NB_N256, 256>>>();
    k_hist<<<NB_E4, 256>>>(dst);
    k_scanA<<<NB_SCAN, 1024>>>();
    k_scanB<<<1, 32>>>(NB_SCAN);
    k_scanC_prep<<<6250, 256>>>((const float2*)x, p_a);
    k_scatter<<<NB_E4, 256>>>(src, dst);

    const int LB = (NN + 127) / 128;  // 782

    k_layer<false><<<LB, 256>>>(p_a, Wt[0], bt[0], p_b);
    k_layer<false><<<LB, 256>>>(p_b, Wt[1], bt[1], p_a);
    k_layer<false><<<LB, 256>>>(p_a, Wt[2], bt[2], p_b);
    k_layer<true ><<<LB, 256>>>(p_b, Wt[3], bt[3], d_out);
}